// round 14
// baseline (speedup 1.0000x reference)
#include <cuda_runtime.h>
#include <math.h>

#define BS 2
#define SN 512
#define W 64
#define MODES 16
#define PAIRS ((SN*(SN-1))/2)
#define GRID 296
#define NTHR 256

// ---------------- scratch (device globals; no allocation) ----------------
__device__ float g_h [BS*W*SN];
__device__ float g_hT[BS*SN*W];
__device__ float g_a [BS*W*SN];
__device__ float g_aT[BS*SN*W];
__device__ float g_p [BS*W*SN];
__device__ float g_pT[BS*SN*W];
__device__ float g_ux[BS*SN*SN];   // exp(-|p_i - p_j|)
__device__ float g_vr[BS*SN*SN];   // |a_i - a_j|
__device__ float g_Xf[BS*W*MODES*2];
__device__ int   g_vrmax[4*BS];
__device__ float g_cos[SN*MODES];
__device__ float g_sin[SN*MODES];

// ---------------- contention-free grid barrier ----------------
// Arrival: one plain store per block (own slot). Detection: block 0's first
// warp scans slots in parallel. Release: single g_gen store, polled read-only.
// Generations are monotonic across graph replays (re-based on persisted g_gen).
__device__ volatile int g_arrive[GRID];
__device__ volatile int g_gen = 0;

__device__ __forceinline__ void gbar(int& gen) {
    gen++;
    __syncthreads();
    const int tid = threadIdx.x;
    if (blockIdx.x == 0) {
        if (tid < 32) {
            for (int s = 1 + tid; s < GRID; s += 32) {
                while (g_arrive[s] < gen) { }
            }
            __threadfence();
        }
        __syncthreads();
        if (tid == 0) { g_gen = gen; }
        __syncthreads();
    } else {
        if (tid == 0) {
            __threadfence();
            g_arrive[blockIdx.x] = gen;
            while (g_gen < gen) { }
            __threadfence();
        }
        __syncthreads();
    }
}

// ---- 64x64 distance tile via SYRK trick: d^2 = nI + nJ - 2*dot ----
// MODE 0: dst = exp(-d)   MODE 1: dst = d, track per-(l,b) max
template<int MODE>
__device__ __forceinline__ void dist_tile(const float* __restrict__ src,
                                          float* __restrict__ dst,
                                          int b, int tile, float* sb, int l) {
    float* sI = sb;
    float* sJ = sb + 4096;
    float* nI = sb + 8192;
    float* nJ = sb + 8256;
    int* smax = (int*)(sb + 8320);
    const int tid = threadIdx.x;
    const int I0 = (tile >> 3) << 6, J0 = (tile & 7) << 6;

    for (int e = tid; e < 1024; e += NTHR) {
        int c = e >> 4, q = e & 15;
        ((float4*)sI)[c*16 + q] = *(const float4*)(src + (b*W + c)*SN + I0 + q*4);
        ((float4*)sJ)[c*16 + q] = *(const float4*)(src + (b*W + c)*SN + J0 + q*4);
    }
    if (MODE == 1 && tid == 0) *smax = 0;
    __syncthreads();
    if (tid < 64) {
        float s = 0.f;
        #pragma unroll 16
        for (int c = 0; c < W; c++) { float v = sI[c*64 + tid]; s += v*v; }
        nI[tid] = s;
    } else if (tid < 128) {
        int t = tid - 64;
        float s = 0.f;
        #pragma unroll 16
        for (int c = 0; c < W; c++) { float v = sJ[c*64 + t]; s += v*v; }
        nJ[t] = s;
    }
    __syncthreads();

    const int tx = tid & 15, ty = tid >> 4;
    float acc[4][4] = {};
    #pragma unroll 4
    for (int c = 0; c < W; c++) {
        float4 ri = *(const float4*)(sI + c*64 + ty*4);
        float4 rj = *(const float4*)(sJ + c*64 + tx*4);
        float riv[4] = {ri.x, ri.y, ri.z, ri.w};
        float rjv[4] = {rj.x, rj.y, rj.z, rj.w};
        #pragma unroll
        for (int r = 0; r < 4; r++)
            #pragma unroll
            for (int s = 0; s < 4; s++)
                acc[r][s] += riv[r] * rjv[s];
    }

    float vmax = 0.f;
    #pragma unroll
    for (int r = 0; r < 4; r++) {
        int row = ty*4 + r;
        float nr = nI[row];
        float ov[4];
        #pragma unroll
        for (int s = 0; s < 4; s++) {
            float d2 = nr + nJ[tx*4 + s] - 2.f*acc[r][s];
            float d = sqrtf(fmaxf(d2, 0.f));
            if (MODE == 0) ov[s] = expf(-d);
            else { ov[s] = d; vmax = fmaxf(vmax, d); }
        }
        *(float4*)(dst + ((size_t)b*SN + I0 + row)*SN + J0 + tx*4) =
            make_float4(ov[0], ov[1], ov[2], ov[3]);
    }
    if (MODE == 1) {
        #pragma unroll
        for (int o2 = 16; o2; o2 >>= 1)
            vmax = fmaxf(vmax, __shfl_down_sync(0xffffffffu, vmax, o2));
        if ((tid & 31) == 0) atomicMax(smax, __float_as_int(vmax));
        __syncthreads();
        if (tid == 0) atomicMax(&g_vrmax[l*BS + b], *smax);
    }
    __syncthreads();
}

extern "C" __global__ void __launch_bounds__(NTHR, 2)
mega(const float* __restrict__ x, const float* __restrict__ vecs,
     const float* __restrict__ fc0_w, const float* __restrict__ fc0_b,
     const float* __restrict__ spec_w, const float* __restrict__ conv_w,
     const float* __restrict__ conv_b, const float* __restrict__ fc1_w,
     const float* __restrict__ fc1_b, const float* __restrict__ fc2_w,
     const float* __restrict__ fc2_b, float* __restrict__ out)
{
    __shared__ __align__(16) float sb[8448];   // 33.8 KB, aliased per phase
    const int tid  = threadIdx.x;
    const int lane = tid & 31;
    const int wp   = tid >> 5;
    int gen = g_gen;   // re-base generation (stable before first barrier)

    // ================= phase 0: trig tables, vrmax reset, fc0 =================
    for (int t = blockIdx.x*NTHR + tid; t < SN*MODES; t += GRID*NTHR) {
        int j = t >> 4, k = t & 15;
        int ph = (j * k) & (SN - 1);
        double ang = (double)ph * (6.283185307179586476925286766559 / (double)SN);
        g_cos[t] = (float)cos(ang);
        g_sin[t] = (float)sin(ang);
    }
    for (int t = blockIdx.x*NTHR + tid; t < 4*BS; t += GRID*NTHR) g_vrmax[t] = 0;
    for (int e = blockIdx.x*NTHR + tid; e < BS*W*SN; e += GRID*NTHR) {
        int bb = e / (W*SN);
        int r  = e - bb*(W*SN);
        int c  = r >> 9;
        int j  = r & (SN-1);
        float x0 = x[(bb*SN + j)*2 + 0];
        float x1 = x[(bb*SN + j)*2 + 1];
        g_h[e] = x0*fc0_w[c] + x1*fc0_w[W + c] + fc0_b[c];
    }
    gbar(gen);

    for (int l = 0; l < 4; l++) {
        // ===== Phase A: DFT (0..127) + 1x1 conv (128..255) =====
        for (int task = blockIdx.x; task < 256; task += GRID) {
            if (task < 128) {
                int bc = task;
                for (int e = tid; e < SN; e += NTHR) sb[e] = g_h[bc*SN + e];
                __syncthreads();
                int m0 = wp, m1 = wp + 8;
                float re0=0.f, im0=0.f, re1=0.f, im1=0.f;
                for (int j = lane; j < SN; j += 32) {
                    float hv = sb[j];
                    re0 += hv * g_cos[j*MODES + m0]; im0 -= hv * g_sin[j*MODES + m0];
                    re1 += hv * g_cos[j*MODES + m1]; im1 -= hv * g_sin[j*MODES + m1];
                }
                #pragma unroll
                for (int o = 16; o; o >>= 1) {
                    re0 += __shfl_down_sync(0xffffffffu, re0, o);
                    im0 += __shfl_down_sync(0xffffffffu, im0, o);
                    re1 += __shfl_down_sync(0xffffffffu, re1, o);
                    im1 += __shfl_down_sync(0xffffffffu, im1, o);
                }
                if (lane == 0) {
                    g_Xf[(bc*MODES + m0)*2 + 0] = re0;
                    g_Xf[(bc*MODES + m0)*2 + 1] = im0;
                    g_Xf[(bc*MODES + m1)*2 + 0] = re1;
                    g_Xf[(bc*MODES + m1)*2 + 1] = im1;
                }
                __syncthreads();
            } else {
                int t2 = task - 128;
                int b = t2 >> 6, o = t2 & 63;
                if (tid < W) sb[tid] = conv_w[((size_t)l*W + o)*W + tid];
                __syncthreads();
                float bias = conv_b[l*W + o];
                for (int j = tid; j < SN; j += NTHR) {
                    float acc = bias;
                    #pragma unroll 16
                    for (int c = 0; c < W; c++) acc += sb[c] * g_h[(b*W + c)*SN + j];
                    g_p [(b*W + o)*SN + j] = acc;
                    g_pT[((size_t)b*SN + j)*W + o] = acc;
                }
                __syncthreads();
            }
        }
        gbar(gen);

        // ===== Phase B: mix+synth only (128 tasks) =====
        {
            const float2* wl2 = (const float2*)(spec_w + (size_t)l*W*W*MODES*2);
            for (int task = blockIdx.x; task < 128; task += GRID) {
                int b = task >> 6, o = task & 63;
                for (int e = tid; e < W*MODES*2; e += NTHR) sb[e] = g_Xf[b*W*MODES*2 + e];
                __syncthreads();
                int k0 = wp, k1 = wp + 8;
                float yr0=0.f, yi0=0.f, yr1=0.f, yi1=0.f;
                for (int i = lane; i < W; i += 32) {
                    float2 w0 = wl2[(i*W + o)*MODES + k0];
                    float2 w1 = wl2[(i*W + o)*MODES + k1];
                    float xr0 = sb[(i*MODES + k0)*2], xi0 = sb[(i*MODES + k0)*2 + 1];
                    float xr1 = sb[(i*MODES + k1)*2], xi1 = sb[(i*MODES + k1)*2 + 1];
                    yr0 += xr0*w0.x - xi0*w0.y;  yi0 += xr0*w0.y + xi0*w0.x;
                    yr1 += xr1*w1.x - xi1*w1.y;  yi1 += xr1*w1.y + xi1*w1.x;
                }
                #pragma unroll
                for (int o2 = 16; o2; o2 >>= 1) {
                    yr0 += __shfl_down_sync(0xffffffffu, yr0, o2);
                    yi0 += __shfl_down_sync(0xffffffffu, yi0, o2);
                    yr1 += __shfl_down_sync(0xffffffffu, yr1, o2);
                    yi1 += __shfl_down_sync(0xffffffffu, yi1, o2);
                }
                if (lane == 0) {
                    sb[2048 + k0*2] = yr0; sb[2048 + k0*2 + 1] = yi0;
                    sb[2048 + k1*2] = yr1; sb[2048 + k1*2 + 1] = yi1;
                }
                __syncthreads();
                for (int j = tid; j < SN; j += NTHR) {
                    float acc = sb[2048];
                    #pragma unroll
                    for (int k = 1; k < MODES; k++)
                        acc += 2.f*(sb[2048 + 2*k]*g_cos[j*MODES + k]
                                  - sb[2048 + 2*k + 1]*g_sin[j*MODES + k]);
                    float a = acc * (1.0f/(float)SN);
                    g_a [(b*W + o)*SN + j] = a;
                    g_aT[((size_t)b*SN + j)*W + o] = a;
                }
                __syncthreads();
            }
        }
        gbar(gen);

        // ===== Phase C: ux tiles (0..127, from p) + vr tiles (128..255, from a) =====
        for (int task = blockIdx.x; task < 256; task += GRID) {
            if (task < 128)
                dist_tile<0>(g_p, g_ux, task >> 6, task & 63, sb, l);
            else {
                int t2 = task - 128;
                dist_tile<1>(g_a, g_vr, t2 >> 6, t2 & 63, sb, l);
            }
        }
        gbar(gen);

        // ===== Phase D: DSMC collide (1024 column tasks) =====
        {
            int*   s_idx = (int*)sb;            // 512
            int*   s_pid = (int*)sb + 512;      // 512
            float* s_wt  = sb + 1024;           // 512
            float* sMx   = sb + 1536;           // 256
            float* sMv   = sb + 1792;           // 256
            int*   ctl   = (int*)(sb + 2304);   // 17
            float* sRc   = sb + 2432;           // 64 (per-channel proj sums)
            int relu = (l < 3);
            for (int task = blockIdx.x; task < BS*SN; task += GRID) {
                int b = task >> 9, j = task & 511;
                __syncthreads();
                if (tid == 0) ctl[0] = 0;
                float thr = 0.1f * __int_as_float(g_vrmax[l*BS + b]);
                const float* vrrow = g_vr + ((size_t)b*SN + j)*SN;
                const float* uxrow = g_ux + ((size_t)b*SN + j)*SN;
                __syncthreads();

                // block-wide ordered compaction (R5 structure)
                for (int base = 0; base < SN; base += NTHR) {
                    int i = base + tid;
                    float vr = vrrow[i];
                    bool pred = (vr * uxrow[i]) > thr;
                    unsigned m = __ballot_sync(0xffffffffu, pred);
                    if (lane == 0) ctl[1 + wp] = __popc(m);
                    __syncthreads();
                    if (tid == 0) {
                        int s0 = ctl[0];
                        #pragma unroll
                        for (int q = 0; q < 8; q++) { ctl[9+q] = s0; s0 += ctl[1+q]; }
                        ctl[0] = s0;
                    }
                    __syncthreads();
                    if (pred) {
                        int pos = ctl[9 + wp] + __popc(m & ((1u << lane) - 1u));
                        int lo = i < j ? i : j, hi = i < j ? j : i;
                        s_idx[pos] = i;
                        s_pid[pos] = lo*SN - (lo*(lo+1))/2 + hi - lo - 1;
                        s_wt [pos] = (i < j) ? vr : -vr;
                    }
                    __syncthreads();
                }

                int n = ctl[0];

                // --- Mx/Mv: c-major (coalesced, L2-resident) ---
                int c = tid & 63, g = tid >> 6;
                float mx = 0.f, mv = 0.f;
                const float* pTb = g_pT + (size_t)b*SN*W + c;
                const float* aTb = g_aT + (size_t)b*SN*W + c;
                for (int k = g; k < n; k += 4) {
                    int i = s_idx[k];
                    mx += pTb[(size_t)i*W];
                    mv += aTb[(size_t)i*W];
                }
                sMx[tid] = mx; sMv[tid] = mv;

                // --- vecs projection: lanes sweep list entries, warp owns 8 channels ---
                {
                    const float* vbase = vecs + ((size_t)l*BS + b)*W*(size_t)PAIRS
                                       + (size_t)(wp*8)*PAIRS;
                    float acc0=0.f, acc1=0.f, acc2=0.f, acc3=0.f;
                    float acc4=0.f, acc5=0.f, acc6=0.f, acc7=0.f;
                    for (int k0 = 0; k0 < n; k0 += 32) {
                        int k = k0 + lane;
                        bool act = k < n;
                        int   pid = act ? s_pid[k] : 0;
                        float wt  = act ? s_wt [k] : 0.f;
                        acc0 += wt * vbase[pid];
                        acc1 += wt * vbase[(size_t)1*PAIRS + pid];
                        acc2 += wt * vbase[(size_t)2*PAIRS + pid];
                        acc3 += wt * vbase[(size_t)3*PAIRS + pid];
                        acc4 += wt * vbase[(size_t)4*PAIRS + pid];
                        acc5 += wt * vbase[(size_t)5*PAIRS + pid];
                        acc6 += wt * vbase[(size_t)6*PAIRS + pid];
                        acc7 += wt * vbase[(size_t)7*PAIRS + pid];
                    }
                    #pragma unroll
                    for (int o2 = 16; o2; o2 >>= 1) {
                        acc0 += __shfl_down_sync(0xffffffffu, acc0, o2);
                        acc1 += __shfl_down_sync(0xffffffffu, acc1, o2);
                        acc2 += __shfl_down_sync(0xffffffffu, acc2, o2);
                        acc3 += __shfl_down_sync(0xffffffffu, acc3, o2);
                        acc4 += __shfl_down_sync(0xffffffffu, acc4, o2);
                        acc5 += __shfl_down_sync(0xffffffffu, acc5, o2);
                        acc6 += __shfl_down_sync(0xffffffffu, acc6, o2);
                        acc7 += __shfl_down_sync(0xffffffffu, acc7, o2);
                    }
                    if (lane == 0) {
                        sRc[wp*8 + 0] = acc0; sRc[wp*8 + 1] = acc1;
                        sRc[wp*8 + 2] = acc2; sRc[wp*8 + 3] = acc3;
                        sRc[wp*8 + 4] = acc4; sRc[wp*8 + 5] = acc5;
                        sRc[wp*8 + 6] = acc6; sRc[wp*8 + 7] = acc7;
                    }
                }
                __syncthreads();

                if (tid < W) {
                    float Mx = sMx[tid] + sMx[tid+64] + sMx[tid+128] + sMx[tid+192];
                    float Mv = sMv[tid] + sMv[tid+64] + sMv[tid+128] + sMv[tid+192];
                    float R  = sRc[tid];
                    float Sc = (float)n;
                    float aj = g_aT[((size_t)b*SN + j)*W + tid];
                    float pj = g_pT[((size_t)b*SN + j)*W + tid];
                    float vnew = aj + 0.5f*aj*Sc - 0.5f*Mv + R;
                    float C = Sc + 1.0f;
                    float xnew = (Mx + pj + pj*C) / (2.0f*C);
                    float h = xnew + vnew;
                    if (relu) h = fmaxf(h, 0.0f);
                    g_h [(b*W + tid)*SN + j] = h;
                    g_hT[((size_t)b*SN + j)*W + tid] = h;
                }
                __syncthreads();
            }
        }
        gbar(gen);
    }

    // ================= head: relu(h@fc1+b1)@fc2+b2 =================
    for (int task = blockIdx.x; task < 512; task += GRID) {
        int b = task >> 8, sp = task & 255;
        int half = tid >> 7, m = tid & 127;
        int s = sp*2 + half;
        __syncthreads();
        if (tid < 128) {
            int hh = tid >> 6, i = tid & 63;
            sb[tid] = g_hT[((size_t)b*SN + (sp*2 + hh))*W + i];
        }
        __syncthreads();
        float acc = fc1_b[m];
        #pragma unroll 16
        for (int cc = 0; cc < W; cc++) acc += sb[half*64 + cc] * fc1_w[cc*128 + m];
        acc = fmaxf(acc, 0.0f) * fc2_w[m];
        sb[128 + tid] = acc;
        __syncthreads();
        #pragma unroll
        for (int o2 = 64; o2; o2 >>= 1) {
            if (m < o2) sb[128 + half*128 + m] += sb[128 + half*128 + m + o2];
            __syncthreads();
        }
        if (m == 0) out[b*SN + s] = sb[128 + half*128] + fc2_b[0];
    }
}

// ---------------- launch ----------------
extern "C" void kernel_launch(void* const* d_in, const int* in_sizes, int n_in,
                              void* d_out, int out_size) {
    const float* x      = (const float*)d_in[0];
    const float* vecs   = (const float*)d_in[2];
    const float* fc0_w  = (const float*)d_in[3];
    const float* fc0_b  = (const float*)d_in[4];
    const float* spec_w = (const float*)d_in[5];
    const float* conv_w = (const float*)d_in[6];
    const float* conv_b = (const float*)d_in[7];
    const float* fc1_w  = (const float*)d_in[8];
    const float* fc1_b  = (const float*)d_in[9];
    const float* fc2_w  = (const float*)d_in[10];
    const float* fc2_b  = (const float*)d_in[11];
    float* out = (float*)d_out;

    mega<<<GRID, NTHR>>>(x, vecs, fc0_w, fc0_b, spec_w, conv_w, conv_b,
                         fc1_w, fc1_b, fc2_w, fc2_b, out);
}

// round 15
// speedup vs baseline: 1.2317x; 1.2317x over previous
#include <cuda_runtime.h>
#include <math.h>

#define BS 2
#define SN 512
#define W 64
#define MODES 16
#define PAIRS ((SN*(SN-1))/2)
#define GRID 296
#define NTHR 512

// ---------------- scratch (device globals; no allocation) ----------------
__device__ float g_h [BS*W*SN];
__device__ float g_hT[BS*SN*W];
__device__ float g_a [BS*W*SN];
__device__ float g_aT[BS*SN*W];
__device__ float g_p [BS*W*SN];
__device__ float g_pT[BS*SN*W];
__device__ float g_ux[BS*SN*SN];   // exp(-|p_i - p_j|)
__device__ float g_vr[BS*SN*SN];   // |a_i - a_j|
__device__ float g_Xf[BS*W*MODES*2];
__device__ int   g_vrmax[4*BS];
__device__ float g_cos[SN*MODES];
__device__ float g_sin[SN*MODES];

// ---------------- grid-wide barrier (atomic busy spin — proven fastest) ----
__device__ int          g_count = 0;
__device__ volatile int g_gen   = 0;

__device__ __forceinline__ void gbar() {
    __syncthreads();
    if (threadIdx.x == 0) {
        __threadfence();
        int my = g_gen;
        if (atomicAdd(&g_count, 1) == GRID - 1) {
            g_count = 0;
            __threadfence();
            g_gen = my + 1;
        } else {
            while (g_gen == my) { }
        }
        __threadfence();
    }
    __syncthreads();
}

// ---- 64x64 distance tile via SYRK trick, 512 threads, 8 outputs/thread ----
// MODE 0: dst = exp(-d)   MODE 1: dst = d, track per-(l,b) max
template<int MODE>
__device__ __forceinline__ void dist_tile(const float* __restrict__ src,
                                          float* __restrict__ dst,
                                          int b, int tile, float* sb, int l) {
    float* sI = sb;
    float* sJ = sb + 4096;
    float* nI = sb + 8192;
    float* nJ = sb + 8256;
    int* smax = (int*)(sb + 8320);
    const int tid = threadIdx.x;
    const int I0 = (tile >> 3) << 6, J0 = (tile & 7) << 6;

    for (int e = tid; e < 1024; e += NTHR) {
        int c = e >> 4, q = e & 15;
        ((float4*)sI)[c*16 + q] = *(const float4*)(src + (b*W + c)*SN + I0 + q*4);
        ((float4*)sJ)[c*16 + q] = *(const float4*)(src + (b*W + c)*SN + J0 + q*4);
    }
    if (MODE == 1 && tid == 0) *smax = 0;
    __syncthreads();
    if (tid < 64) {
        float s = 0.f;
        #pragma unroll 16
        for (int c = 0; c < W; c++) { float v = sI[c*64 + tid]; s += v*v; }
        nI[tid] = s;
    } else if (tid < 128) {
        int t = tid - 64;
        float s = 0.f;
        #pragma unroll 16
        for (int c = 0; c < W; c++) { float v = sJ[c*64 + t]; s += v*v; }
        nJ[t] = s;
    }
    __syncthreads();

    const int tx = tid & 15, ty = tid >> 4;   // ty in 0..31; rows ty, ty+32
    float acc[2][4] = {};
    #pragma unroll 4
    for (int c = 0; c < W; c++) {
        float r0 = sI[c*64 + ty];
        float r1 = sI[c*64 + ty + 32];
        float4 rj = *(const float4*)(sJ + c*64 + tx*4);
        float rjv[4] = {rj.x, rj.y, rj.z, rj.w};
        #pragma unroll
        for (int s = 0; s < 4; s++) {
            acc[0][s] += r0 * rjv[s];
            acc[1][s] += r1 * rjv[s];
        }
    }

    float vmax = 0.f;
    #pragma unroll
    for (int r = 0; r < 2; r++) {
        int row = ty + 32*r;
        float nr = nI[row];
        float ov[4];
        #pragma unroll
        for (int s = 0; s < 4; s++) {
            float d2 = nr + nJ[tx*4 + s] - 2.f*acc[r][s];
            float d = sqrtf(fmaxf(d2, 0.f));
            if (MODE == 0) ov[s] = expf(-d);
            else { ov[s] = d; vmax = fmaxf(vmax, d); }
        }
        *(float4*)(dst + ((size_t)b*SN + I0 + row)*SN + J0 + tx*4) =
            make_float4(ov[0], ov[1], ov[2], ov[3]);
    }
    if (MODE == 1) {
        #pragma unroll
        for (int o2 = 16; o2; o2 >>= 1)
            vmax = fmaxf(vmax, __shfl_down_sync(0xffffffffu, vmax, o2));
        if ((tid & 31) == 0) atomicMax(smax, __float_as_int(vmax));
        __syncthreads();
        if (tid == 0) atomicMax(&g_vrmax[l*BS + b], *smax);
    }
    __syncthreads();
}

extern "C" __global__ void __launch_bounds__(NTHR, 2)
mega(const float* __restrict__ x, const float* __restrict__ vecs,
     const float* __restrict__ fc0_w, const float* __restrict__ fc0_b,
     const float* __restrict__ spec_w, const float* __restrict__ conv_w,
     const float* __restrict__ conv_b, const float* __restrict__ fc1_w,
     const float* __restrict__ fc1_b, const float* __restrict__ fc2_w,
     const float* __restrict__ fc2_b, float* __restrict__ out)
{
    __shared__ __align__(16) float sb[8448];   // 33.8 KB, aliased per phase
    const int tid  = threadIdx.x;
    const int lane = tid & 31;
    const int wp   = tid >> 5;                 // 16 warps

    // ================= phase 0: trig tables, vrmax reset, fc0 =================
    for (int t = blockIdx.x*NTHR + tid; t < SN*MODES; t += GRID*NTHR) {
        int j = t >> 4, k = t & 15;
        int ph = (j * k) & (SN - 1);
        double ang = (double)ph * (6.283185307179586476925286766559 / (double)SN);
        g_cos[t] = (float)cos(ang);
        g_sin[t] = (float)sin(ang);
    }
    for (int t = blockIdx.x*NTHR + tid; t < 4*BS; t += GRID*NTHR) g_vrmax[t] = 0;
    for (int e = blockIdx.x*NTHR + tid; e < BS*W*SN; e += GRID*NTHR) {
        int bb = e / (W*SN);
        int r  = e - bb*(W*SN);
        int c  = r >> 9;
        int j  = r & (SN-1);
        float x0 = x[(bb*SN + j)*2 + 0];
        float x1 = x[(bb*SN + j)*2 + 1];
        g_h[e] = x0*fc0_w[c] + x1*fc0_w[W + c] + fc0_b[c];
    }
    gbar();

    for (int l = 0; l < 4; l++) {
        // ===== Phase A: DFT (0..127) + 1x1 conv (128..255) =====
        for (int task = blockIdx.x; task < 256; task += GRID) {
            if (task < 128) {
                int bc = task;
                sb[tid] = g_h[bc*SN + tid];      // 512 elems, 1/thread
                __syncthreads();
                int m0 = wp;                      // 16 warps = 16 modes
                float re0 = 0.f, im0 = 0.f;
                for (int j = lane; j < SN; j += 32) {
                    float hv = sb[j];
                    re0 += hv * g_cos[j*MODES + m0];
                    im0 -= hv * g_sin[j*MODES + m0];
                }
                #pragma unroll
                for (int o = 16; o; o >>= 1) {
                    re0 += __shfl_down_sync(0xffffffffu, re0, o);
                    im0 += __shfl_down_sync(0xffffffffu, im0, o);
                }
                if (lane == 0) {
                    g_Xf[(bc*MODES + m0)*2 + 0] = re0;
                    g_Xf[(bc*MODES + m0)*2 + 1] = im0;
                }
                __syncthreads();
            } else {
                int t2 = task - 128;
                int b = t2 >> 6, o = t2 & 63;
                if (tid < W) sb[tid] = conv_w[((size_t)l*W + o)*W + tid];
                __syncthreads();
                int j = tid;                      // one j per thread
                float acc = conv_b[l*W + o];
                #pragma unroll 16
                for (int c = 0; c < W; c++) acc += sb[c] * g_h[(b*W + c)*SN + j];
                g_p [(b*W + o)*SN + j] = acc;
                g_pT[((size_t)b*SN + j)*W + o] = acc;
                __syncthreads();
            }
        }
        gbar();

        // ===== Phase B: mix+synth only (128 tasks) =====
        {
            const float2* wl2 = (const float2*)(spec_w + (size_t)l*W*W*MODES*2);
            for (int task = blockIdx.x; task < 128; task += GRID) {
                int b = task >> 6, o = task & 63;
                if (tid < W*MODES*2) sb[tid] = g_Xf[b*W*MODES*2 + tid];  // 2048
                if (tid + 512  < W*MODES*2) sb[tid + 512]  = g_Xf[b*W*MODES*2 + tid + 512];
                if (tid + 1024 < W*MODES*2) sb[tid + 1024] = g_Xf[b*W*MODES*2 + tid + 1024];
                if (tid + 1536 < W*MODES*2) sb[tid + 1536] = g_Xf[b*W*MODES*2 + tid + 1536];
                __syncthreads();
                int k0 = wp;                       // 16 warps = 16 modes
                float yr0 = 0.f, yi0 = 0.f;
                for (int i = lane; i < W; i += 32) {
                    float2 w0 = wl2[(i*W + o)*MODES + k0];
                    float xr0 = sb[(i*MODES + k0)*2], xi0 = sb[(i*MODES + k0)*2 + 1];
                    yr0 += xr0*w0.x - xi0*w0.y;
                    yi0 += xr0*w0.y + xi0*w0.x;
                }
                #pragma unroll
                for (int o2 = 16; o2; o2 >>= 1) {
                    yr0 += __shfl_down_sync(0xffffffffu, yr0, o2);
                    yi0 += __shfl_down_sync(0xffffffffu, yi0, o2);
                }
                if (lane == 0) {
                    sb[2048 + k0*2]     = yr0;
                    sb[2048 + k0*2 + 1] = yi0;
                }
                __syncthreads();
                int j = tid;                       // one j per thread
                float acc = sb[2048];
                #pragma unroll
                for (int k = 1; k < MODES; k++)
                    acc += 2.f*(sb[2048 + 2*k]*g_cos[j*MODES + k]
                              - sb[2048 + 2*k + 1]*g_sin[j*MODES + k]);
                float a = acc * (1.0f/(float)SN);
                g_a [(b*W + o)*SN + j] = a;
                g_aT[((size_t)b*SN + j)*W + o] = a;
                __syncthreads();
            }
        }
        gbar();

        // ===== Phase C: ux tiles (0..127, from p) + vr tiles (128..255, from a) =====
        for (int task = blockIdx.x; task < 256; task += GRID) {
            if (task < 128)
                dist_tile<0>(g_p, g_ux, task >> 6, task & 63, sb, l);
            else {
                int t2 = task - 128;
                dist_tile<1>(g_a, g_vr, t2 >> 6, t2 & 63, sb, l);
            }
        }
        gbar();

        // ===== Phase D: DSMC collide (1024 column tasks), single-pass compaction =====
        {
            int*   s_idx = (int*)sb;              // 512
            int*   s_pid = (int*)sb + 512;        // 512
            float* s_wt  = sb + 1024;             // 512
            float* sMx   = sb + 1536;             // 512
            float* sMv   = sb + 2048;             // 512
            float* sRc   = sb + 2560;             // 64
            int*   ctl   = (int*)(sb + 2624);     // [0]=n [1..16]=wcnt [17..32]=wbase
            int relu = (l < 3);
            for (int task = blockIdx.x; task < BS*SN; task += GRID) {
                int b = task >> 9, j = task & 511;
                __syncthreads();
                float thr = 0.1f * __int_as_float(g_vrmax[l*BS + b]);
                const float* vrrow = g_vr + ((size_t)b*SN + j)*SN;
                const float* uxrow = g_ux + ((size_t)b*SN + j)*SN;

                // one ballot pass: 512 threads cover all 512 i's
                {
                    int i = tid;
                    float vr = vrrow[i];
                    bool pred = (vr * uxrow[i]) > thr;
                    unsigned m = __ballot_sync(0xffffffffu, pred);
                    if (lane == 0) ctl[1 + wp] = __popc(m);
                    __syncthreads();
                    if (tid == 0) {
                        int s0 = 0;
                        #pragma unroll
                        for (int q = 0; q < 16; q++) { ctl[17+q] = s0; s0 += ctl[1+q]; }
                        ctl[0] = s0;
                    }
                    __syncthreads();
                    if (pred) {
                        int pos = ctl[17 + wp] + __popc(m & ((1u << lane) - 1u));
                        int lo = i < j ? i : j, hi = i < j ? j : i;
                        s_idx[pos] = i;
                        s_pid[pos] = lo*SN - (lo*(lo+1))/2 + hi - lo - 1;
                        s_wt [pos] = (i < j) ? vr : -vr;
                    }
                    __syncthreads();
                }

                int n = ctl[0];

                // --- Mx/Mv: c-major (coalesced, L2-resident), 8 k-groups ---
                int c = tid & 63, g = tid >> 6;
                float mx = 0.f, mv = 0.f;
                const float* pTb = g_pT + (size_t)b*SN*W + c;
                const float* aTb = g_aT + (size_t)b*SN*W + c;
                for (int k = g; k < n; k += 8) {
                    int i = s_idx[k];
                    mx += pTb[(size_t)i*W];
                    mv += aTb[(size_t)i*W];
                }
                sMx[tid] = mx; sMv[tid] = mv;

                // --- vecs projection: lanes sweep entries, warp owns 4 channels ---
                {
                    const float* vbase = vecs + ((size_t)l*BS + b)*W*(size_t)PAIRS
                                       + (size_t)(wp*4)*PAIRS;
                    float acc0=0.f, acc1=0.f, acc2=0.f, acc3=0.f;
                    for (int k0 = 0; k0 < n; k0 += 32) {
                        int k = k0 + lane;
                        bool act = k < n;
                        int   pid = act ? s_pid[k] : 0;
                        float wt  = act ? s_wt [k] : 0.f;
                        acc0 += wt * vbase[pid];
                        acc1 += wt * vbase[(size_t)1*PAIRS + pid];
                        acc2 += wt * vbase[(size_t)2*PAIRS + pid];
                        acc3 += wt * vbase[(size_t)3*PAIRS + pid];
                    }
                    #pragma unroll
                    for (int o2 = 16; o2; o2 >>= 1) {
                        acc0 += __shfl_down_sync(0xffffffffu, acc0, o2);
                        acc1 += __shfl_down_sync(0xffffffffu, acc1, o2);
                        acc2 += __shfl_down_sync(0xffffffffu, acc2, o2);
                        acc3 += __shfl_down_sync(0xffffffffu, acc3, o2);
                    }
                    if (lane == 0) {
                        sRc[wp*4 + 0] = acc0; sRc[wp*4 + 1] = acc1;
                        sRc[wp*4 + 2] = acc2; sRc[wp*4 + 3] = acc3;
                    }
                }
                __syncthreads();

                if (tid < W) {
                    float Mx = 0.f, Mv = 0.f;
                    #pragma unroll
                    for (int q = 0; q < 8; q++) { Mx += sMx[tid + 64*q]; Mv += sMv[tid + 64*q]; }
                    float R  = sRc[tid];
                    float Sc = (float)n;
                    float aj = g_aT[((size_t)b*SN + j)*W + tid];
                    float pj = g_pT[((size_t)b*SN + j)*W + tid];
                    float vnew = aj + 0.5f*aj*Sc - 0.5f*Mv + R;
                    float C = Sc + 1.0f;
                    float xnew = (Mx + pj + pj*C) / (2.0f*C);
                    float h = xnew + vnew;
                    if (relu) h = fmaxf(h, 0.0f);
                    g_h [(b*W + tid)*SN + j] = h;
                    g_hT[((size_t)b*SN + j)*W + tid] = h;
                }
                __syncthreads();
            }
        }
        gbar();
    }

    // ================= head: 4 rows per task (256 tasks) =================
    for (int task = blockIdx.x; task < 256; task += GRID) {
        int b = task >> 7, sp = task & 127;
        int q = tid >> 7, m = tid & 127;       // 4 row-groups of 128 threads
        int s = sp*4 + q;
        __syncthreads();
        if (tid < 256) {
            int qq = tid >> 6, i = tid & 63;
            sb[tid] = g_hT[((size_t)b*SN + (sp*4 + qq))*W + i];
        }
        __syncthreads();
        float acc = fc1_b[m];
        #pragma unroll 16
        for (int cc = 0; cc < W; cc++) acc += sb[q*64 + cc] * fc1_w[cc*128 + m];
        acc = fmaxf(acc, 0.0f) * fc2_w[m];
        sb[256 + tid] = acc;
        __syncthreads();
        #pragma unroll
        for (int o2 = 64; o2; o2 >>= 1) {
            if (m < o2) sb[256 + q*128 + m] += sb[256 + q*128 + m + o2];
            __syncthreads();
        }
        if (m == 0) out[b*SN + s] = sb[256 + q*128] + fc2_b[0];
    }
}

// ---------------- launch ----------------
extern "C" void kernel_launch(void* const* d_in, const int* in_sizes, int n_in,
                              void* d_out, int out_size) {
    const float* x      = (const float*)d_in[0];
    const float* vecs   = (const float*)d_in[2];
    const float* fc0_w  = (const float*)d_in[3];
    const float* fc0_b  = (const float*)d_in[4];
    const float* spec_w = (const float*)d_in[5];
    const float* conv_w = (const float*)d_in[6];
    const float* conv_b = (const float*)d_in[7];
    const float* fc1_w  = (const float*)d_in[8];
    const float* fc1_b  = (const float*)d_in[9];
    const float* fc2_w  = (const float*)d_in[10];
    const float* fc2_b  = (const float*)d_in[11];
    float* out = (float*)d_out;

    mega<<<GRID, NTHR>>>(x, vecs, fc0_w, fc0_b, spec_w, conv_w, conv_b,
                         fc1_w, fc1_b, fc2_w, fc2_b, out);
}